// round 5
// baseline (speedup 1.0000x reference)
#include <cuda_runtime.h>
#include <cstdint>

// Problem constants
#define B_    512
#define C_    10
#define HW_   4096          // 64*64
#define W_    64
#define NWIN  3969          // 63*63
#define SRN   128           // strategic_reasoning row length
#define THREADS 256
#define BITWORDS 313        // ceil(10000/32)

// ---------------- per-block result arrays (written every run; no init) ------
__device__ float         a_focal[B_];   // weighted focal sum per batch
__device__ float         a_creat[B_];   // sigmoid sum per batch
__device__ unsigned int  a_eq[B_];      // eq count per batch
__device__ unsigned int  a_cp[B_];      // copy-eq count per batch
__device__ unsigned int  a_un[B_];      // unique 2x2 codes per batch
__device__ unsigned int  g_count = 0;   // completion counter (reset by last block)

// ---------------- helpers ---------------------------------------------------
__device__ __forceinline__ float warpSumF(float v) {
#pragma unroll
    for (int o = 16; o; o >>= 1) v += __shfl_down_sync(0xffffffffu, v, o);
    return v;
}
__device__ __forceinline__ double warpSumD(double v) {
#pragma unroll
    for (int o = 16; o; o >>= 1) v += __shfl_down_sync(0xffffffffu, v, o);
    return v;
}
__device__ __forceinline__ unsigned warpSumU(unsigned v) {
#pragma unroll
    for (int o = 16; o; o >>= 1) v += __shfl_down_sync(0xffffffffu, v, o);
    return v;
}
__device__ __forceinline__ unsigned warpOrU(unsigned v) {
#pragma unroll
    for (int o = 16; o; o >>= 1) v |= __shfl_down_sync(0xffffffffu, v, o);
    return v;
}

// ---------------- single fused kernel ---------------------------------------
__global__ __launch_bounds__(THREADS)
void minerva_main_kernel(const float* __restrict__ pred,
                         const int*   __restrict__ targets,
                         const int*   __restrict__ inputs,
                         const float* __restrict__ sr,
                         float*       __restrict__ out) {
    __shared__ unsigned char s_pred[HW_];
    __shared__ unsigned int  s_bitmap[BITWORDS];
    __shared__ float         s_f[8];
    __shared__ double        s_d[8];
    __shared__ double        s_d2[8];
    __shared__ unsigned int  s_u[8];
    __shared__ unsigned int  s_u2[8];
    __shared__ unsigned int  s_u3[8];
    __shared__ unsigned int  s_u4[8];
    __shared__ unsigned int  s_present;
    __shared__ int           s_last;

    const int b    = blockIdx.x;
    const int tid  = threadIdx.x;
    const int lane = tid & 31;
    const int wid  = tid >> 5;

    if (tid == 0) s_present = 0u;
    __syncthreads();

    const float* pb = pred    + (size_t)b * C_ * HW_;
    const int*   tb = targets + (size_t)b * HW_;
    const int*   ib = inputs  + (size_t)b * HW_;

    float    focal_local = 0.f;
    unsigned eq_local = 0u, cp_local = 0u, pmask = 0u;

#pragma unroll
    for (int i = 0; i < 4; i++) {
        const int g = tid + i * THREADS;               // group of 4 pixels

        // ---- pass 0: issue all loads up front (10 independent LDG.128) ----
        float va[C_][4];
#pragma unroll
        for (int c = 0; c < C_; c++) {
            float4 v = reinterpret_cast<const float4*>(pb + (size_t)c * HW_)[g];
            va[c][0] = v.x; va[c][1] = v.y; va[c][2] = v.z; va[c][3] = v.w;
        }
        int4 tt = reinterpret_cast<const int4*>(tb)[g];
        int4 ii = reinterpret_cast<const int4*>(ib)[g];
        int t[4]  = {tt.x, tt.y, tt.z, tt.w};
        int ip[4] = {ii.x, ii.y, ii.z, ii.w};

        unsigned char pj[4];
#pragma unroll
        for (int j = 0; j < 4; j++) {
            float x[C_];
#pragma unroll
            for (int c = 0; c < C_; c++) x[c] = va[c][j];

            // max tree (9 fmax, fully parallel)
            float m01 = fmaxf(x[0], x[1]);
            float m23 = fmaxf(x[2], x[3]);
            float m45 = fmaxf(x[4], x[5]);
            float m67 = fmaxf(x[6], x[7]);
            float m89 = fmaxf(x[8], x[9]);
            float m = fmaxf(fmaxf(fmaxf(m01, m23), fmaxf(m45, m67)), m89);

            // first-max argmax: descending scan, smallest c with x[c]==m wins
            int bi = 0;
#pragma unroll
            for (int c = C_ - 1; c >= 0; --c) bi = (x[c] == m) ? c : bi;

            // v_target via select chain (no runtime register indexing)
            float vt = x[0];
#pragma unroll
            for (int c = 1; c < C_; ++c) vt = (t[j] == c) ? x[c] : vt;

            // independent exps + tree sum
            float e[C_];
#pragma unroll
            for (int c = 0; c < C_; ++c) e[c] = __expf(x[c] - m);
            float s = (((e[0] + e[1]) + (e[2] + e[3])) +
                       ((e[4] + e[5]) + (e[6] + e[7]))) + (e[8] + e[9]);

            float ce = __logf(s) + m - vt;
            float pt = __expf(-ce);
            float om = 1.f - pt;
            focal_local += om * om * ce;
            eq_local += (bi == t[j]);
            cp_local += (bi == ip[j]);
            pmask |= 1u << t[j];
            pj[j] = (unsigned char)bi;
        }
        reinterpret_cast<uchar4*>(s_pred)[g] = make_uchar4(pj[0], pj[1], pj[2], pj[3]);
    }

    // target-color presence mask (per batch)
    pmask = warpOrU(pmask);
    if (lane == 0) atomicOr(&s_present, pmask);

    // creativity: thread t<128 handles sr[b*128 + t]
    float creat_local = 0.f;
    if (tid < SRN) {
        float x = sr[(size_t)b * SRN + tid];
        creat_local = __fdividef(1.f, 1.f + __expf(-x));
    }

    // ---- block reductions ----
    float fsum   = warpSumF(focal_local);
    float crsum  = warpSumF(creat_local);
    unsigned es  = warpSumU(eq_local);
    unsigned cs  = warpSumU(cp_local);
    if (lane == 0) { s_f[wid] = fsum; s_d[wid] = (double)crsum; s_u[wid] = es; s_u2[wid] = cs; }
    __syncthreads();

    // ---- diversity: unique 2x2 codes via presence bitmap ----
    for (int k = tid; k < BITWORDS; k += THREADS) s_bitmap[k] = 0u;
    __syncthreads();   // also orders s_pred writes before reads below

    for (int idx = tid; idx < NWIN; idx += THREADS) {
        int h = idx / 63, w = idx - h * 63;
        int base = h * W_ + w;
        int p00 = s_pred[base];
        int p01 = s_pred[base + 1];
        int p10 = s_pred[base + W_];
        int p11 = s_pred[base + W_ + 1];
        int code = p00 * 1000 + p01 * 100 + p10 * 10 + p11;
        atomicOr(&s_bitmap[code >> 5], 1u << (code & 31));
    }
    __syncthreads();

    unsigned cnt = 0u;
    for (int k = tid; k < BITWORDS; k += THREADS) cnt += __popc(s_bitmap[k]);
    cnt = warpSumU(cnt);
    if (lane == 0) s_u3[wid] = cnt;
    __syncthreads();

    // ---- publish per-batch results, detect last block ----
    if (tid == 0) {
        float ft = 0.f; double cr = 0.0;
        unsigned eu = 0u, cu = 0u, un = 0u;
        for (int k = 0; k < 8; k++) {
            ft += s_f[k]; cr += s_d[k]; eu += s_u[k]; cu += s_u2[k]; un += s_u3[k];
        }
        float w = (__popc(s_present) > 3) ? 1.2f : 1.0f;
        a_focal[b] = ft * w;
        a_creat[b] = (float)cr;
        a_eq[b]    = eu;
        a_cp[b]    = cu;
        a_un[b]    = un;
        __threadfence();
        unsigned prev = atomicAdd(&g_count, 1u);
        s_last = (prev == (unsigned)(B_ - 1));
    }
    __syncthreads();
    if (!s_last) return;

    // ================= last block: finalize =================
    if (tid == 0) g_count = 0;     // reset early for next graph replay

    double f = 0.0, cr = 0.0;
    unsigned eq = 0u, st = 0u, cp = 0u, un = 0u;
    for (int k = tid; k < B_; k += THREADS) {
        f  += (double)a_focal[k];
        cr += (double)a_creat[k];
        unsigned e = a_eq[k];
        eq += e;
        st += (e == HW_);
        cp += (a_cp[k] == HW_);
        un += a_un[k];
    }
    f  = warpSumD(f);
    cr = warpSumD(cr);
    eq = warpSumU(eq);
    st = warpSumU(st);
    cp = warpSumU(cp);
    un = warpSumU(un);
    if (lane == 0) {
        s_d[wid] = f; s_d2[wid] = cr;
        s_u[wid] = eq; s_u2[wid] = cp; s_u3[wid] = un; s_u4[wid] = st;
    }
    __syncthreads();

    if (tid == 0) {
        double F = 0.0, CR = 0.0;
        unsigned EQ = 0u, ST = 0u, CP = 0u, UN = 0u;
        for (int k = 0; k < 8; k++) {
            F += s_d[k]; CR += s_d2[k];
            EQ += s_u[k]; ST += s_u4[k]; CP += s_u2[k]; UN += s_u3[k];
        }

        const double NPIX = (double)B_ * (double)HW_;
        double focal       = F / NPIX;
        double iou_mean    = (double)EQ / NPIX;
        double exact_count = 0.2 * (double)ST + 0.8 * ((double)EQ / (double)HW_);
        double comb_mean   = exact_count / (double)B_;
        double exact_bonus = fmax(-comb_mean * 5.0, -3.0);
        double transform_p = ((double)CP / (double)B_) * 0.2;
        double creat       = (CR / ((double)B_ * SRN)) * 0.15;
        double divers      = ((double)UN / (double)NWIN) / (double)B_ * 0.02;
        double grid_bonus  = comb_mean * 0.05;   // grid_size_factor == 1 for 64x64

        double total = focal + transform_p + exact_bonus - creat - divers - grid_bonus;
        if (isnan(total) || isinf(total)) total = fmin(focal, 10.0);

        out[0] = (float)total;
        out[1] = (float)focal;
        out[2] = (float)transform_p;
        out[3] = (float)exact_bonus;
        out[4] = (float)exact_count;
        out[5] = (float)exact_count;   // combined_matches.sum() == exact_count
        out[6] = (float)iou_mean;
        out[7] = (float)creat;
        out[8] = (float)divers;
        out[9] = (float)grid_bonus;
    }
}

// ---------------- launch -----------------------------------------------------
extern "C" void kernel_launch(void* const* d_in, const int* in_sizes, int n_in,
                              void* d_out, int out_size) {
    const float* pred    = (const float*)d_in[0];
    const int*   targets = (const int*)d_in[1];
    const int*   inputs  = (const int*)d_in[2];
    const float* sr      = (const float*)d_in[3];
    float*       out     = (float*)d_out;

    minerva_main_kernel<<<B_, THREADS>>>(pred, targets, inputs, sr, out);
}

// round 6
// speedup vs baseline: 1.2519x; 1.2519x over previous
#include <cuda_runtime.h>
#include <cstdint>

// Problem constants
#define B_    512
#define C_    10
#define HW_   4096          // 64*64
#define W_    64
#define NWIN  3969          // 63*63
#define SRN   128           // strategic_reasoning row length
#define THREADS 256
#define BITWORDS 313        // ceil(10000/32)

// ---------------- per-block result arrays (written every run; no init) ------
__device__ float         a_focal[B_];   // weighted focal sum per batch
__device__ float         a_creat[B_];   // sigmoid sum per batch
__device__ unsigned int  a_eq[B_];      // eq count per batch
__device__ unsigned int  a_cp[B_];      // copy-eq count per batch
__device__ unsigned int  a_un[B_];      // unique 2x2 codes per batch
__device__ unsigned int  g_count = 0;   // completion counter (reset by last block)

// ---------------- helpers ---------------------------------------------------
__device__ __forceinline__ float warpSumF(float v) {
#pragma unroll
    for (int o = 16; o; o >>= 1) v += __shfl_down_sync(0xffffffffu, v, o);
    return v;
}
__device__ __forceinline__ double warpSumD(double v) {
#pragma unroll
    for (int o = 16; o; o >>= 1) v += __shfl_down_sync(0xffffffffu, v, o);
    return v;
}
__device__ __forceinline__ unsigned warpSumU(unsigned v) {
#pragma unroll
    for (int o = 16; o; o >>= 1) v += __shfl_down_sync(0xffffffffu, v, o);
    return v;
}
__device__ __forceinline__ unsigned warpOrU(unsigned v) {
#pragma unroll
    for (int o = 16; o; o >>= 1) v |= __shfl_down_sync(0xffffffffu, v, o);
    return v;
}

// online logsumexp + argmax update, single-MUFU form:
//   nm = max(m,v); one of exp(m-nm), exp(v-nm) is exp(0)=1, so
//   e = exp(-|v-m|); s = (v>m) ? s*e + 1 : s + e
// The MUFU feeds off the fast fmax chain; the s-recurrence is a short FFMA/FADD+SEL.
__device__ __forceinline__ void upd(float& m, float& s, int& bi, float& vt,
                                    float v, int c, int t) {
    float e  = __expf(-fabsf(v - m));
    bool  gt = (v > m);
    s  = gt ? __fmaf_rn(s, e, 1.0f) : (s + e);
    if (gt) bi = c;                 // strict > keeps the FIRST max (jnp.argmax)
    m  = fmaxf(m, v);
    if (c == t) vt = v;
}

// ---------------- single fused kernel ---------------------------------------
__global__ __launch_bounds__(THREADS)
void minerva_main_kernel(const float* __restrict__ pred,
                         const int*   __restrict__ targets,
                         const int*   __restrict__ inputs,
                         const float* __restrict__ sr,
                         float*       __restrict__ out) {
    __shared__ unsigned char s_pred[HW_];
    __shared__ unsigned int  s_bitmap[BITWORDS];
    __shared__ float         s_f[8];
    __shared__ double        s_d[8];
    __shared__ double        s_d2[8];
    __shared__ unsigned int  s_u[8];
    __shared__ unsigned int  s_u2[8];
    __shared__ unsigned int  s_u3[8];
    __shared__ unsigned int  s_u4[8];
    __shared__ unsigned int  s_present;
    __shared__ int           s_last;

    const int b    = blockIdx.x;
    const int tid  = threadIdx.x;
    const int lane = tid & 31;
    const int wid  = tid >> 5;

    if (tid == 0) s_present = 0u;
    __syncthreads();

    const float* pb = pred    + (size_t)b * C_ * HW_;
    const int*   tb = targets + (size_t)b * HW_;
    const int*   ib = inputs  + (size_t)b * HW_;

    float    focal_local = 0.f;
    unsigned eq_local = 0u, cp_local = 0u, pmask = 0u;

#pragma unroll
    for (int i = 0; i < 4; i++) {
        const int g = tid + i * THREADS;               // group of 4 pixels
        float4 v0 = reinterpret_cast<const float4*>(pb)[g];
        int4   tt = reinterpret_cast<const int4*>(tb)[g];
        int4   ii = reinterpret_cast<const int4*>(ib)[g];

        float m[4]  = {v0.x, v0.y, v0.z, v0.w};
        float s[4]  = {1.f, 1.f, 1.f, 1.f};
        float vt[4] = {v0.x, v0.y, v0.z, v0.w};        // valid iff t==0, else overwritten
        int   bi[4] = {0, 0, 0, 0};
        int   t[4]  = {tt.x, tt.y, tt.z, tt.w};
        int   ip[4] = {ii.x, ii.y, ii.z, ii.w};

#pragma unroll
        for (int c = 1; c < C_; c++) {
            float4 v = reinterpret_cast<const float4*>(pb + (size_t)c * HW_)[g];
            float va[4] = {v.x, v.y, v.z, v.w};
#pragma unroll
            for (int j = 0; j < 4; j++) upd(m[j], s[j], bi[j], vt[j], va[j], c, t[j]);
        }

        unsigned char pj[4];
#pragma unroll
        for (int j = 0; j < 4; j++) {
            float ce = m[j] + __logf(s[j]) - vt[j];
            float pt = __expf(-ce);
            float om = 1.f - pt;
            focal_local += om * om * ce;
            eq_local += (bi[j] == t[j]);
            cp_local += (bi[j] == ip[j]);
            pmask |= 1u << t[j];
            pj[j] = (unsigned char)bi[j];
        }
        reinterpret_cast<uchar4*>(s_pred)[g] = make_uchar4(pj[0], pj[1], pj[2], pj[3]);
    }

    // target-color presence mask (per batch)
    pmask = warpOrU(pmask);
    if (lane == 0) atomicOr(&s_present, pmask);

    // creativity: thread t<128 handles sr[b*128 + t]
    float creat_local = 0.f;
    if (tid < SRN) {
        float x = sr[(size_t)b * SRN + tid];
        creat_local = __fdividef(1.f, 1.f + __expf(-x));
    }

    // ---- block reductions ----
    float fsum   = warpSumF(focal_local);
    float crsum  = warpSumF(creat_local);
    unsigned es  = warpSumU(eq_local);
    unsigned cs  = warpSumU(cp_local);
    if (lane == 0) { s_f[wid] = fsum; s_d[wid] = (double)crsum; s_u[wid] = es; s_u2[wid] = cs; }
    __syncthreads();

    // ---- diversity: unique 2x2 codes via presence bitmap ----
    for (int k = tid; k < BITWORDS; k += THREADS) s_bitmap[k] = 0u;
    __syncthreads();   // also orders s_pred writes before reads below

    for (int idx = tid; idx < NWIN; idx += THREADS) {
        int h = idx / 63, w = idx - h * 63;
        int base = h * W_ + w;
        int p00 = s_pred[base];
        int p01 = s_pred[base + 1];
        int p10 = s_pred[base + W_];
        int p11 = s_pred[base + W_ + 1];
        int code = p00 * 1000 + p01 * 100 + p10 * 10 + p11;
        atomicOr(&s_bitmap[code >> 5], 1u << (code & 31));
    }
    __syncthreads();

    unsigned cnt = 0u;
    for (int k = tid; k < BITWORDS; k += THREADS) cnt += __popc(s_bitmap[k]);
    cnt = warpSumU(cnt);
    if (lane == 0) s_u3[wid] = cnt;
    __syncthreads();

    // ---- publish per-batch results, detect last block ----
    if (tid == 0) {
        float ft = 0.f; double cr = 0.0;
        unsigned eu = 0u, cu = 0u, un = 0u;
        for (int k = 0; k < 8; k++) {
            ft += s_f[k]; cr += s_d[k]; eu += s_u[k]; cu += s_u2[k]; un += s_u3[k];
        }
        float w = (__popc(s_present) > 3) ? 1.2f : 1.0f;
        a_focal[b] = ft * w;
        a_creat[b] = (float)cr;
        a_eq[b]    = eu;
        a_cp[b]    = cu;
        a_un[b]    = un;
        __threadfence();
        unsigned prev = atomicAdd(&g_count, 1u);
        s_last = (prev == (unsigned)(B_ - 1));
    }
    __syncthreads();
    if (!s_last) return;

    // ================= last block: finalize =================
    if (tid == 0) g_count = 0;     // reset early for next graph replay

    double f = 0.0, cr = 0.0;
    unsigned eq = 0u, st = 0u, cp = 0u, un = 0u;
    for (int k = tid; k < B_; k += THREADS) {
        f  += (double)a_focal[k];
        cr += (double)a_creat[k];
        unsigned e = a_eq[k];
        eq += e;
        st += (e == HW_);
        cp += (a_cp[k] == HW_);
        un += a_un[k];
    }
    f  = warpSumD(f);
    cr = warpSumD(cr);
    eq = warpSumU(eq);
    st = warpSumU(st);
    cp = warpSumU(cp);
    un = warpSumU(un);
    if (lane == 0) {
        s_d[wid] = f; s_d2[wid] = cr;
        s_u[wid] = eq; s_u2[wid] = cp; s_u3[wid] = un; s_u4[wid] = st;
    }
    __syncthreads();

    if (tid == 0) {
        double F = 0.0, CR = 0.0;
        unsigned EQ = 0u, ST = 0u, CP = 0u, UN = 0u;
        for (int k = 0; k < 8; k++) {
            F += s_d[k]; CR += s_d2[k];
            EQ += s_u[k]; ST += s_u4[k]; CP += s_u2[k]; UN += s_u3[k];
        }

        const double NPIX = (double)B_ * (double)HW_;
        double focal       = F / NPIX;
        double iou_mean    = (double)EQ / NPIX;
        double exact_count = 0.2 * (double)ST + 0.8 * ((double)EQ / (double)HW_);
        double comb_mean   = exact_count / (double)B_;
        double exact_bonus = fmax(-comb_mean * 5.0, -3.0);
        double transform_p = ((double)CP / (double)B_) * 0.2;
        double creat       = (CR / ((double)B_ * SRN)) * 0.15;
        double divers      = ((double)UN / (double)NWIN) / (double)B_ * 0.02;
        double grid_bonus  = comb_mean * 0.05;   // grid_size_factor == 1 for 64x64

        double total = focal + transform_p + exact_bonus - creat - divers - grid_bonus;
        if (isnan(total) || isinf(total)) total = fmin(focal, 10.0);

        out[0] = (float)total;
        out[1] = (float)focal;
        out[2] = (float)transform_p;
        out[3] = (float)exact_bonus;
        out[4] = (float)exact_count;
        out[5] = (float)exact_count;   // combined_matches.sum() == exact_count
        out[6] = (float)iou_mean;
        out[7] = (float)creat;
        out[8] = (float)divers;
        out[9] = (float)grid_bonus;
    }
}

// ---------------- launch -----------------------------------------------------
extern "C" void kernel_launch(void* const* d_in, const int* in_sizes, int n_in,
                              void* d_out, int out_size) {
    const float* pred    = (const float*)d_in[0];
    const int*   targets = (const int*)d_in[1];
    const int*   inputs  = (const int*)d_in[2];
    const float* sr      = (const float*)d_in[3];
    float*       out     = (float*)d_out;

    minerva_main_kernel<<<B_, THREADS>>>(pred, targets, inputs, sr, out);
}

// round 9
// speedup vs baseline: 1.5756x; 1.2585x over previous
// MinervaEnhancedLoss fused kernel — R9 resubmit of the R7/R8 build.
// (Source intentionally touched vs R8 to change the content hash; semantics
//  identical. R7/R8 never executed: broker died pre-compile both times.)
#include <cuda_runtime.h>
#include <cstdint>

// Problem constants
#define B_    512
#define C_    10
#define HW_   4096          // 64*64
#define W_    64
#define NWIN  3969          // 63*63
#define SRN   128           // strategic_reasoning row length
#define THREADS 256
#define BITWORDS 313        // ceil(10000/32)

// ---------------- per-block result arrays (written every run; no init) ------
__device__ float         a_focal[B_];   // weighted focal sum per batch
__device__ float         a_creat[B_];   // sigmoid sum per batch
__device__ unsigned int  a_eq[B_];      // eq count per batch
__device__ unsigned int  a_cp[B_];      // copy-eq count per batch
__device__ unsigned int  a_un[B_];      // unique 2x2 codes per batch
__device__ unsigned int  g_count = 0;   // completion counter (reset by last block)

// ---------------- helpers ---------------------------------------------------
__device__ __forceinline__ float warpSumF(float v) {
#pragma unroll
    for (int o = 16; o; o >>= 1) v += __shfl_down_sync(0xffffffffu, v, o);
    return v;
}
__device__ __forceinline__ double warpSumD(double v) {
#pragma unroll
    for (int o = 16; o; o >>= 1) v += __shfl_down_sync(0xffffffffu, v, o);
    return v;
}
__device__ __forceinline__ unsigned warpSumU(unsigned v) {
#pragma unroll
    for (int o = 16; o; o >>= 1) v += __shfl_down_sync(0xffffffffu, v, o);
    return v;
}
__device__ __forceinline__ unsigned warpOrU(unsigned v) {
#pragma unroll
    for (int o = 16; o; o >>= 1) v |= __shfl_down_sync(0xffffffffu, v, o);
    return v;
}

// Online logsumexp + argmax, single-MUFU recurrence:
//   nm = max(m,v); exactly one of exp(m-nm), exp(v-nm) equals 1, so
//   e = exp(-|v-m|);  s = (v>m) ? fma(s,e,1) : s+e
// MUFU hangs off the fast fmax chain; the serial s-step is SEL/FFMA (~5cyc).
__device__ __forceinline__ void upd(float& m, float& s, int& bi, float& vt,
                                    float v, int c, int t) {
    float e  = __expf(-fabsf(v - m));
    bool  gt = (v > m);
    s  = gt ? __fmaf_rn(s, e, 1.0f) : (s + e);
    if (gt) bi = c;                 // strict > keeps FIRST max (jnp.argmax)
    m  = fmaxf(m, v);
    if (c == t) vt = v;
}

// ---------------- single fused kernel ---------------------------------------
// minBlocks=4 forces <=64 regs/thread: recovers the 4-CTA/SM occupancy that
// the 71-reg R6 build lost (4->3 CTAs cost more than its cheaper math saved).
__global__ __launch_bounds__(THREADS, 4)
void minerva_fused_kernel(const float* __restrict__ pred,
                          const int*   __restrict__ targets,
                          const int*   __restrict__ inputs,
                          const float* __restrict__ sr,
                          float*       __restrict__ out) {
    __shared__ unsigned char s_pred[HW_];
    __shared__ unsigned int  s_bitmap[BITWORDS];
    __shared__ float         s_f[8];
    __shared__ double        s_d[8];
    __shared__ double        s_d2[8];
    __shared__ unsigned int  s_u[8];
    __shared__ unsigned int  s_u2[8];
    __shared__ unsigned int  s_u3[8];
    __shared__ unsigned int  s_u4[8];
    __shared__ unsigned int  s_present;
    __shared__ int           s_last;

    const int b    = blockIdx.x;
    const int tid  = threadIdx.x;
    const int lane = tid & 31;
    const int wid  = tid >> 5;

    if (tid == 0) s_present = 0u;
    __syncthreads();

    const float* pb = pred    + (size_t)b * C_ * HW_;
    const int*   tb = targets + (size_t)b * HW_;
    const int*   ib = inputs  + (size_t)b * HW_;

    float    focal_local = 0.f;
    unsigned eq_local = 0u, cp_local = 0u, pmask = 0u;

#pragma unroll
    for (int i = 0; i < 4; i++) {
        const int g = tid + i * THREADS;               // group of 4 pixels
        float4 v0 = reinterpret_cast<const float4*>(pb)[g];
        int4   tt = reinterpret_cast<const int4*>(tb)[g];
        int4   ii = reinterpret_cast<const int4*>(ib)[g];

        float m[4]  = {v0.x, v0.y, v0.z, v0.w};
        float s[4]  = {1.f, 1.f, 1.f, 1.f};
        float vt[4] = {v0.x, v0.y, v0.z, v0.w};        // valid iff t==0, else overwritten
        int   bi[4] = {0, 0, 0, 0};
        int   t[4]  = {tt.x, tt.y, tt.z, tt.w};
        int   ip[4] = {ii.x, ii.y, ii.z, ii.w};

#pragma unroll
        for (int c = 1; c < C_; c++) {
            float4 v = reinterpret_cast<const float4*>(pb + (size_t)c * HW_)[g];
            float va[4] = {v.x, v.y, v.z, v.w};
#pragma unroll
            for (int j = 0; j < 4; j++) upd(m[j], s[j], bi[j], vt[j], va[j], c, t[j]);
        }

        unsigned char pj[4];
#pragma unroll
        for (int j = 0; j < 4; j++) {
            float ce = m[j] + __logf(s[j]) - vt[j];
            float pt = __expf(-ce);
            float om = 1.f - pt;
            focal_local += om * om * ce;
            eq_local += (bi[j] == t[j]);
            cp_local += (bi[j] == ip[j]);
            pmask |= 1u << t[j];
            pj[j] = (unsigned char)bi[j];
        }
        reinterpret_cast<uchar4*>(s_pred)[g] = make_uchar4(pj[0], pj[1], pj[2], pj[3]);
    }

    // target-color presence mask (per batch)
    pmask = warpOrU(pmask);
    if (lane == 0) atomicOr(&s_present, pmask);

    // creativity: threads [0,128) handle sr[b*128 + tid]
    float creat_local = 0.f;
    if (tid < SRN) {
        float x = sr[(size_t)b * SRN + tid];
        creat_local = __fdividef(1.f, 1.f + __expf(-x));
    }

    // ---- block reductions ----
    float fsum   = warpSumF(focal_local);
    float crsum  = warpSumF(creat_local);
    unsigned es  = warpSumU(eq_local);
    unsigned cs  = warpSumU(cp_local);
    if (lane == 0) { s_f[wid] = fsum; s_d[wid] = (double)crsum; s_u[wid] = es; s_u2[wid] = cs; }
    __syncthreads();

    // ---- diversity: unique 2x2 codes via presence bitmap ----
    for (int k = tid; k < BITWORDS; k += THREADS) s_bitmap[k] = 0u;
    __syncthreads();   // also orders s_pred writes before reads below

    for (int idx = tid; idx < NWIN; idx += THREADS) {
        int h = idx / 63, w = idx - h * 63;
        int base = h * W_ + w;
        int p00 = s_pred[base];
        int p01 = s_pred[base + 1];
        int p10 = s_pred[base + W_];
        int p11 = s_pred[base + W_ + 1];
        int code = p00 * 1000 + p01 * 100 + p10 * 10 + p11;
        atomicOr(&s_bitmap[code >> 5], 1u << (code & 31));
    }
    __syncthreads();

    unsigned cnt = 0u;
    for (int k = tid; k < BITWORDS; k += THREADS) cnt += __popc(s_bitmap[k]);
    cnt = warpSumU(cnt);
    if (lane == 0) s_u3[wid] = cnt;
    __syncthreads();

    // ---- publish per-batch results, detect last block ----
    if (tid == 0) {
        float ft = 0.f; double cr = 0.0;
        unsigned eu = 0u, cu = 0u, un = 0u;
        for (int k = 0; k < 8; k++) {
            ft += s_f[k]; cr += s_d[k]; eu += s_u[k]; cu += s_u2[k]; un += s_u3[k];
        }
        float w = (__popc(s_present) > 3) ? 1.2f : 1.0f;
        a_focal[b] = ft * w;
        a_creat[b] = (float)cr;
        a_eq[b]    = eu;
        a_cp[b]    = cu;
        a_un[b]    = un;
        __threadfence();
        unsigned prev = atomicAdd(&g_count, 1u);
        s_last = (prev == (unsigned)(B_ - 1));
    }
    __syncthreads();
    if (!s_last) return;

    // ================= last block: finalize =================
    if (tid == 0) g_count = 0;     // reset early for next graph replay

    double f = 0.0, cr = 0.0;
    unsigned eq = 0u, st = 0u, cp = 0u, un = 0u;
    for (int k = tid; k < B_; k += THREADS) {
        f  += (double)a_focal[k];
        cr += (double)a_creat[k];
        unsigned e = a_eq[k];
        eq += e;
        st += (e == HW_);
        cp += (a_cp[k] == HW_);
        un += a_un[k];
    }
    f  = warpSumD(f);
    cr = warpSumD(cr);
    eq = warpSumU(eq);
    st = warpSumU(st);
    cp = warpSumU(cp);
    un = warpSumU(un);
    if (lane == 0) {
        s_d[wid] = f; s_d2[wid] = cr;
        s_u[wid] = eq; s_u2[wid] = cp; s_u3[wid] = un; s_u4[wid] = st;
    }
    __syncthreads();

    if (tid == 0) {
        double F = 0.0, CR = 0.0;
        unsigned EQ = 0u, ST = 0u, CP = 0u, UN = 0u;
        for (int k = 0; k < 8; k++) {
            F += s_d[k]; CR += s_d2[k];
            EQ += s_u[k]; ST += s_u4[k]; CP += s_u2[k]; UN += s_u3[k];
        }

        const double NPIX = (double)B_ * (double)HW_;
        double focal       = F / NPIX;
        double iou_mean    = (double)EQ / NPIX;
        double exact_count = 0.2 * (double)ST + 0.8 * ((double)EQ / (double)HW_);
        double comb_mean   = exact_count / (double)B_;
        double exact_bonus = fmax(-comb_mean * 5.0, -3.0);
        double transform_p = ((double)CP / (double)B_) * 0.2;
        double creat       = (CR / ((double)B_ * SRN)) * 0.15;
        double divers      = ((double)UN / (double)NWIN) / (double)B_ * 0.02;
        double grid_bonus  = comb_mean * 0.05;   // grid_size_factor == 1 for 64x64

        double total = focal + transform_p + exact_bonus - creat - divers - grid_bonus;
        if (isnan(total) || isinf(total)) total = fmin(focal, 10.0);

        out[0] = (float)total;
        out[1] = (float)focal;
        out[2] = (float)transform_p;
        out[3] = (float)exact_bonus;
        out[4] = (float)exact_count;
        out[5] = (float)exact_count;   // combined_matches.sum() == exact_count
        out[6] = (float)iou_mean;
        out[7] = (float)creat;
        out[8] = (float)divers;
        out[9] = (float)grid_bonus;
    }
}

// ---------------- launch -----------------------------------------------------
extern "C" void kernel_launch(void* const* d_in, const int* in_sizes, int n_in,
                              void* d_out, int out_size) {
    const float* pred    = (const float*)d_in[0];
    const int*   targets = (const int*)d_in[1];
    const int*   inputs  = (const int*)d_in[2];
    const float* sr      = (const float*)d_in[3];
    float*       out     = (float*)d_out;

    minerva_fused_kernel<<<B_, THREADS>>>(pred, targets, inputs, sr, out);
}